// round 9
// baseline (speedup 1.0000x reference)
#include <cuda_runtime.h>
#include <cuda_bf16.h>

#define LL     1024
#define SSQ    1024
#define MMEM   256
#define NBATCH 8
#define EDIM   512
#define NHEAD  8
#define HDIM   64
#define NH     64        // NBATCH * NHEAD
#define RTOT   8192      // LL * NBATCH

// ---------------- device-global scratch (the only legal scratch) -----------
static __device__ float g_q[NH * LL * HDIM];               // [nh][l][d]
static __device__ float g_k[NH * SSQ * HDIM];              // [nh][s][d]
static __device__ float g_v[NH * SSQ * HDIM];              // [nh][s][d]
static __device__ float g_sc[(size_t)NH * LL * SSQ];       // exp(scores) 256MB
static __device__ float g_csum[NH * SSQ];                  // column sums
static __device__ float g_attn[NH * LL * HDIM];            // main-branch attn
static __device__ float g_ctx[(size_t)RTOT * EDIM];        // [l*8+n][e]
static __device__ unsigned char g_mask[NBATCH * MMEM];     // decoded bool mask

__device__ __forceinline__ float warp_sum32(float x) {
    x += __shfl_xor_sync(0xffffffffu, x, 16);
    x += __shfl_xor_sync(0xffffffffu, x, 8);
    x += __shfl_xor_sync(0xffffffffu, x, 4);
    x += __shfl_xor_sync(0xffffffffu, x, 2);
    x += __shfl_xor_sync(0xffffffffu, x, 1);
    return x;
}

// ============================================================================
// K0: decode mem_mask regardless of upload encoding (uint8 / int32 / float32 /
// bf16). Sniff encoding from the first 512 words (2048 bytes — safe for all).
// ============================================================================
__global__ __launch_bounds__(256) void mask_decode_kernel(
    const unsigned int* __restrict__ m)
{
    __shared__ int enc_flags;   // bit0: 1-byte packed, bit1: bf16
    if (threadIdx.x == 0) enc_flags = 0;
    __syncthreads();
    for (int i = threadIdx.x; i < 512; i += 256) {
        unsigned int w = m[i];
        if ((w & 0xFFFFu) == 0x3F80u) atomicOr(&enc_flags, 2);        // bf16
        else if ((w >> 8) != 0 && w != 0x3F800000u) atomicOr(&enc_flags, 1);
    }
    __syncthreads();
    int f = enc_flags;
    if (f & 2) {            // bfloat16: halfword per element
        const unsigned short* mh = (const unsigned short*)m;
        for (int i = threadIdx.x; i < NBATCH * MMEM; i += 256)
            g_mask[i] = mh[i] ? 1 : 0;
    } else if (f & 1) {     // packed 1-byte (numpy bool_)
        const unsigned char* mb = (const unsigned char*)m;
        for (int i = threadIdx.x; i < NBATCH * MMEM; i += 256)
            g_mask[i] = mb[i] ? 1 : 0;
    } else {                // 4-byte: int32 {0,1} or float32 {0.0,1.0}
        for (int i = threadIdx.x; i < NBATCH * MMEM; i += 256)
            g_mask[i] = m[i] ? 1 : 0;
    }
}

// ============================================================================
// K1: fused QKV projection + bias + q-scale + rotary.  Out: [nh][l|s][d].
// 128x128x8 SGEMM tile, 256 threads, 8x8 microtile. blockIdx.z = {q,k,v}.
// ============================================================================
__global__ __launch_bounds__(256) void qkv_kernel(
    const float* __restrict__ Xq, const float* __restrict__ Xk,
    const float* __restrict__ Xv, const float* __restrict__ W,
    const float* __restrict__ Bb, const float* __restrict__ rq,
    const float* __restrict__ rk)
{
    const int mode = blockIdx.z;  // 0=q, 1=k, 2=v
    const float* X   = (mode == 0) ? Xq : (mode == 1) ? Xk : Xv;
    const float* Wm  = W + (size_t)mode * EDIM * EDIM;
    const float* Bm  = Bb + mode * EDIM;
    const float* rot = (mode == 0) ? rq : rk;
    float* dst = (mode == 0) ? g_q : (mode == 1) ? g_k : g_v;

    __shared__ float As[8][132];
    __shared__ float Bs[8][132];

    const int t = threadIdx.x;
    const int row0 = blockIdx.y * 128;
    const int col0 = blockIdx.x * 128;
    const int lrow = t >> 1;
    const int lk = (t & 1) * 4;
    const int ty = t >> 4;
    const int tx = t & 15;

    float acc[8][8] = {};

    const float* Ap = X + (size_t)(row0 + lrow) * EDIM + lk;
    const float* Bp = Wm + (size_t)(col0 + lrow) * EDIM + lk;

    for (int k0 = 0; k0 < EDIM; k0 += 8) {
        float4 av = *(const float4*)(Ap + k0);
        float4 bv = *(const float4*)(Bp + k0);
        __syncthreads();
        As[lk + 0][lrow] = av.x; As[lk + 1][lrow] = av.y;
        As[lk + 2][lrow] = av.z; As[lk + 3][lrow] = av.w;
        Bs[lk + 0][lrow] = bv.x; Bs[lk + 1][lrow] = bv.y;
        Bs[lk + 2][lrow] = bv.z; Bs[lk + 3][lrow] = bv.w;
        __syncthreads();
#pragma unroll
        for (int kk = 0; kk < 8; kk++) {
            float a[8], b[8];
            *(float4*)(a)     = *(const float4*)(&As[kk][ty * 4]);
            *(float4*)(a + 4) = *(const float4*)(&As[kk][64 + ty * 4]);
            *(float4*)(b)     = *(const float4*)(&Bs[kk][tx * 4]);
            *(float4*)(b + 4) = *(const float4*)(&Bs[kk][64 + tx * 4]);
#pragma unroll
            for (int i = 0; i < 8; i++)
#pragma unroll
                for (int j = 0; j < 8; j++)
                    acc[i][j] = fmaf(a[i], b[j], acc[i][j]);
        }
    }

    const float scale = (mode == 0) ? 0.125f : 1.0f;  // hd^-0.5
#pragma unroll
    for (int i = 0; i < 8; i++) {
        int r = row0 + ty * 4 + (i & 3) + ((i >> 2) << 6);
        int l = r >> 3, nn = r & 7;   // X is [L,N,E] row-major
#pragma unroll
        for (int jg = 0; jg < 2; jg++) {
            int e0 = col0 + tx * 4 + jg * 64;
            float4 bb = *(const float4*)(Bm + e0);
            float v0 = (acc[i][jg * 4 + 0] + bb.x) * scale;
            float v1 = (acc[i][jg * 4 + 1] + bb.y) * scale;
            float v2 = (acc[i][jg * 4 + 2] + bb.z) * scale;
            float v3 = (acc[i][jg * 4 + 3] + bb.w) * scale;
            float o0 = v0, o1 = v1, o2 = v2, o3 = v3;
            if (mode < 2) {
                // rot[n][l][e][{cos,sin}]; interleaved rotate-half
                const float* rp = rot + ((size_t)(nn * LL + l) * EDIM + e0) * 2;
                float4 r01 = *(const float4*)(rp);      // c0 s0 c1 s1
                float4 r23 = *(const float4*)(rp + 4);  // c2 s2 c3 s3
                o0 = v0 * r01.x - v1 * r01.y;
                o1 = v1 * r01.z + v0 * r01.w;
                o2 = v2 * r23.x - v3 * r23.y;
                o3 = v3 * r23.z + v2 * r23.w;
            }
            *(float4*)(dst + (size_t)((nn * NHEAD + (e0 >> 6)) * LL + l) * HDIM
                       + (e0 & 63)) = make_float4(o0, o1, o2, o3);
        }
    }
}

// ============================================================================
// K2: g_sc[nh][l][s] = exp( q[nh][l][:] . k[nh][s][:] ).  128x128 tile, K=64.
// exp fused into the GEMM epilogue. Safe without max-sub: |score| <~ 15 << 88.
// ============================================================================
__global__ __launch_bounds__(256) void scores_kernel()
{
    const int nh = blockIdx.z;
    const int l0 = blockIdx.y * 128;
    const int s0 = blockIdx.x * 128;
    const float* A = g_q + (size_t)nh * LL * HDIM;
    const float* B = g_k + (size_t)nh * SSQ * HDIM;
    float* C = g_sc + ((size_t)nh << 20);

    __shared__ float As[16][132];
    __shared__ float Bs[16][132];

    const int t = threadIdx.x;
    const int lrow = t >> 1;
    const int lk = (t & 1) * 8;
    const int ty = t >> 4, tx = t & 15;

    float acc[8][8] = {};

    for (int k0 = 0; k0 < 64; k0 += 16) {
        float4 a0 = *(const float4*)(A + (size_t)(l0 + lrow) * 64 + k0 + lk);
        float4 a1 = *(const float4*)(A + (size_t)(l0 + lrow) * 64 + k0 + lk + 4);
        float4 b0 = *(const float4*)(B + (size_t)(s0 + lrow) * 64 + k0 + lk);
        float4 b1 = *(const float4*)(B + (size_t)(s0 + lrow) * 64 + k0 + lk + 4);
        __syncthreads();
        As[lk + 0][lrow] = a0.x; As[lk + 1][lrow] = a0.y;
        As[lk + 2][lrow] = a0.z; As[lk + 3][lrow] = a0.w;
        As[lk + 4][lrow] = a1.x; As[lk + 5][lrow] = a1.y;
        As[lk + 6][lrow] = a1.z; As[lk + 7][lrow] = a1.w;
        Bs[lk + 0][lrow] = b0.x; Bs[lk + 1][lrow] = b0.y;
        Bs[lk + 2][lrow] = b0.z; Bs[lk + 3][lrow] = b0.w;
        Bs[lk + 4][lrow] = b1.x; Bs[lk + 5][lrow] = b1.y;
        Bs[lk + 6][lrow] = b1.z; Bs[lk + 7][lrow] = b1.w;
        __syncthreads();
#pragma unroll
        for (int kk = 0; kk < 16; kk++) {
            float a[8], b[8];
            *(float4*)(a)     = *(const float4*)(&As[kk][ty * 4]);
            *(float4*)(a + 4) = *(const float4*)(&As[kk][64 + ty * 4]);
            *(float4*)(b)     = *(const float4*)(&Bs[kk][tx * 4]);
            *(float4*)(b + 4) = *(const float4*)(&Bs[kk][64 + tx * 4]);
#pragma unroll
            for (int i = 0; i < 8; i++)
#pragma unroll
                for (int j = 0; j < 8; j++)
                    acc[i][j] = fmaf(a[i], b[j], acc[i][j]);
        }
    }

#pragma unroll
    for (int i = 0; i < 8; i++) {
        int l = l0 + ty * 4 + (i & 3) + ((i >> 2) << 6);
#pragma unroll
        for (int jg = 0; jg < 2; jg++) {
            int s = s0 + tx * 4 + jg * 64;
            *(float4*)(C + (size_t)l * SSQ + s) = make_float4(
                __expf(acc[i][jg * 4 + 0]), __expf(acc[i][jg * 4 + 1]),
                __expf(acc[i][jg * 4 + 2]), __expf(acc[i][jg * 4 + 3]));
        }
    }
}

// ============================================================================
// K3: column sums over l (queries) of exp'd scores — pure memory pass.
// ============================================================================
__global__ __launch_bounds__(256) void colsum_kernel()
{
    const int nh = blockIdx.y;
    const int s = blockIdx.x * 256 + threadIdx.x;
    const float* sc = g_sc + ((size_t)nh << 20) + s;
    float sum = 0.f;
    for (int l = 0; l < LL; l += 8) {
        float x[8];
#pragma unroll
        for (int j = 0; j < 8; j++) x[j] = sc[(size_t)(l + j) * SSQ];
#pragma unroll
        for (int j = 0; j < 8; j++) sum += x[j];
    }
    g_csum[nh * SSQ + s] = sum;
}

// ============================================================================
// K4: main attention. Per (nh, 128-l tile): stream s in 32-chunks,
// w = p/csum_s + 1e-8, rowsum += w, acc += w @ V, normalize by rowsum.
// ============================================================================
__global__ __launch_bounds__(256) void attn_main_kernel()
{
    const int nh = blockIdx.y;
    const int l0 = blockIdx.x * 128;
    const float* sc = g_sc + ((size_t)nh << 20);
    const float* V = g_v + (size_t)nh * SSQ * HDIM;

    __shared__ float ws[32][136];   // [s_local][l_local]
    __shared__ float vs[32][68];    // [s_local][d]
    __shared__ float rowsum[128];

    const int t = threadIdx.x;
    const int warp = t >> 5, lane = t & 31;
    const int ty = t >> 4, tx = t & 15;
    const int vrow = t >> 3, vq = (t & 7) * 8;

    if (t < 128) rowsum[t] = 0.f;

    float acc[8][4] = {};

    for (int s0 = 0; s0 < SSQ; s0 += 32) {
        float ci = 1.f / g_csum[nh * SSQ + s0 + lane];
        float4 v0 = *(const float4*)(V + (size_t)(s0 + vrow) * 64 + vq);
        float4 v1 = *(const float4*)(V + (size_t)(s0 + vrow) * 64 + vq + 4);
        float xv[16];
#pragma unroll
        for (int i = 0; i < 16; i++)
            xv[i] = sc[(size_t)(l0 + warp + 8 * i) * SSQ + s0 + lane];
        __syncthreads();
        *(float4*)(&vs[vrow][vq]) = v0;
        *(float4*)(&vs[vrow][vq + 4]) = v1;
#pragma unroll
        for (int i = 0; i < 16; i++) {
            float w = xv[i] * ci + 1e-8f;
            ws[lane][warp + 8 * i] = w;
            float rs = warp_sum32(w);
            if (lane == 0) rowsum[warp + 8 * i] += rs;
        }
        __syncthreads();
#pragma unroll
        for (int kk = 0; kk < 32; kk++) {
            float a[8], b[4];
            *(float4*)(a)     = *(const float4*)(&ws[kk][ty * 8]);
            *(float4*)(a + 4) = *(const float4*)(&ws[kk][ty * 8 + 4]);
            *(float4*)(b)     = *(const float4*)(&vs[kk][tx * 4]);
#pragma unroll
            for (int i = 0; i < 8; i++)
#pragma unroll
                for (int j = 0; j < 4; j++)
                    acc[i][j] = fmaf(a[i], b[j], acc[i][j]);
        }
    }
    __syncthreads();
    float* dst = g_attn + (size_t)nh * LL * HDIM;
#pragma unroll
    for (int i = 0; i < 8; i++) {
        int r = ty * 8 + i;
        float inv = 1.f / rowsum[r];
        *(float4*)(dst + (size_t)(l0 + r) * 64 + tx * 4) =
            make_float4(acc[i][0] * inv, acc[i][1] * inv,
                        acc[i][2] * inv, acc[i][3] * inv);
    }
}

// ============================================================================
// K5: memory branch + gate combine. Per (nh, 64-l tile): stream m in 32-chunks:
// sm = q@km^T, p = masked exp (no max needed, |sm|<~9), om = p@vm / rowsum,
// out = gate*om + (1-gate)*attn_main, written to g_ctx[l*8+n][e].
// ============================================================================
__global__ __launch_bounds__(256) void attn_mem_kernel(
    const float* __restrict__ kmem, const float* __restrict__ vmem,
    const float* __restrict__ gatew)
{
    const int nh = blockIdx.y;
    const int n = nh >> 3, h = nh & 7;
    const int l0 = blockIdx.x * 64;

    __shared__ float qs[64][68];
    __shared__ float kc[32][68];
    __shared__ float vc[32][68];
    __shared__ float ps[64][34];
    __shared__ float mask_s[256];

    const int t = threadIdx.x;
    const int ty = t >> 4, tx = t & 15;

    {   // q tile [64][64]
        int row = t >> 2;
        int dq = (t & 3) * 16;
        const float* qp = g_q + ((size_t)nh * LL + l0 + row) * HDIM + dq;
#pragma unroll
        for (int j = 0; j < 4; j++)
            *(float4*)(&qs[row][dq + j * 4]) = *(const float4*)(qp + j * 4);
    }
    mask_s[t] = g_mask[n * MMEM + t] ? 1.f : 0.f;
    __syncthreads();

    float acc2[4][4] = {};
    float rsum[4] = {0.f, 0.f, 0.f, 0.f};

    const int mrow = t >> 3, mq = (t & 7) * 8;

    for (int m0 = 0; m0 < MMEM; m0 += 32) {
        const float* kp = kmem + ((size_t)(m0 + mrow) * NBATCH + n) * EDIM + h * 64 + mq;
        const float* vp = vmem + ((size_t)(m0 + mrow) * NBATCH + n) * EDIM + h * 64 + mq;
        float4 kv0 = *(const float4*)(kp);
        float4 kv1 = *(const float4*)(kp + 4);
        float4 vv0 = *(const float4*)(vp);
        float4 vv1 = *(const float4*)(vp + 4);
        __syncthreads();   // previous GEMM2 done with vc/ps
        *(float4*)(&kc[mrow][mq])     = kv0;
        *(float4*)(&kc[mrow][mq + 4]) = kv1;
        *(float4*)(&vc[mrow][mq])     = vv0;
        *(float4*)(&vc[mrow][mq + 4]) = vv1;
        __syncthreads();

        // GEMM1: sm[64 l][32 m] chunk; thread = 4l x 2m
        float a1[4][2] = {};
#pragma unroll
        for (int kk = 0; kk < 64; kk += 4) {
            float4 b0 = *(const float4*)(&kc[tx * 2][kk]);
            float4 b1 = *(const float4*)(&kc[tx * 2 + 1][kk]);
#pragma unroll
            for (int i = 0; i < 4; i++) {
                float4 a = *(const float4*)(&qs[ty * 4 + i][kk]);
                a1[i][0] = fmaf(a.x, b0.x, fmaf(a.y, b0.y,
                           fmaf(a.z, b0.z, fmaf(a.w, b0.w, a1[i][0]))));
                a1[i][1] = fmaf(a.x, b1.x, fmaf(a.y, b1.y,
                           fmaf(a.z, b1.z, fmaf(a.w, b1.w, a1[i][1]))));
            }
        }
        float msk0 = mask_s[m0 + tx * 2];
        float msk1 = mask_s[m0 + tx * 2 + 1];
#pragma unroll
        for (int i = 0; i < 4; i++) {
            float p0 = (msk0 != 0.f) ? 0.f : __expf(a1[i][0]);
            float p1 = (msk1 != 0.f) ? 0.f : __expf(a1[i][1]);
            ps[ty * 4 + i][tx * 2]     = p0;
            ps[ty * 4 + i][tx * 2 + 1] = p1;
            rsum[i] += p0 + p1;
        }
        __syncthreads();

        // GEMM2: acc2[4 l][4 d] += ps @ vc
#pragma unroll
        for (int kk = 0; kk < 32; kk++) {
            float4 b = *(const float4*)(&vc[kk][tx * 4]);
#pragma unroll
            for (int i = 0; i < 4; i++) {
                float a = ps[ty * 4 + i][kk];
                acc2[i][0] = fmaf(a, b.x, acc2[i][0]);
                acc2[i][1] = fmaf(a, b.y, acc2[i][1]);
                acc2[i][2] = fmaf(a, b.z, acc2[i][2]);
                acc2[i][3] = fmaf(a, b.w, acc2[i][3]);
            }
        }
    }

    // reduce rsum across the 16 tx lanes (each half-warp shares a ty)
#pragma unroll
    for (int i = 0; i < 4; i++) {
        float r = rsum[i];
        r += __shfl_xor_sync(0xffffffffu, r, 8);
        r += __shfl_xor_sync(0xffffffffu, r, 4);
        r += __shfl_xor_sync(0xffffffffu, r, 2);
        r += __shfl_xor_sync(0xffffffffu, r, 1);
        rsum[i] = r;
    }

    const float gate = 1.f / (1.f + __expf(-gatew[h]));
    const float omg = 1.f - gate;
#pragma unroll
    for (int i = 0; i < 4; i++) {
        int l = l0 + ty * 4 + i;
        float inv = 1.f / rsum[i];
        float4 am = *(const float4*)(g_attn + ((size_t)nh * LL + l) * 64 + tx * 4);
        float4 o;
        o.x = gate * (acc2[i][0] * inv) + omg * am.x;
        o.y = gate * (acc2[i][1] * inv) + omg * am.y;
        o.z = gate * (acc2[i][2] * inv) + omg * am.z;
        o.w = gate * (acc2[i][3] * inv) + omg * am.w;
        *(float4*)(g_ctx + ((size_t)l * NBATCH + n) * EDIM + h * 64 + tx * 4) = o;
    }
}

// ============================================================================
// K6: output projection out[r][e] = ctx[r][:] . Wout[e][:] + bias[e].
// ============================================================================
__global__ __launch_bounds__(256) void outproj_kernel(
    const float* __restrict__ W, const float* __restrict__ Bv,
    float* __restrict__ out)
{
    __shared__ float As[8][132];
    __shared__ float Bs[8][132];

    const int t = threadIdx.x;
    const int row0 = blockIdx.y * 128;
    const int col0 = blockIdx.x * 128;
    const int lrow = t >> 1;
    const int lk = (t & 1) * 4;
    const int ty = t >> 4, tx = t & 15;

    float acc[8][8] = {};

    const float* Ap = g_ctx + (size_t)(row0 + lrow) * EDIM + lk;
    const float* Bp = W + (size_t)(col0 + lrow) * EDIM + lk;

    for (int k0 = 0; k0 < EDIM; k0 += 8) {
        float4 av = *(const float4*)(Ap + k0);
        float4 bv = *(const float4*)(Bp + k0);
        __syncthreads();
        As[lk + 0][lrow] = av.x; As[lk + 1][lrow] = av.y;
        As[lk + 2][lrow] = av.z; As[lk + 3][lrow] = av.w;
        Bs[lk + 0][lrow] = bv.x; Bs[lk + 1][lrow] = bv.y;
        Bs[lk + 2][lrow] = bv.z; Bs[lk + 3][lrow] = bv.w;
        __syncthreads();
#pragma unroll
        for (int kk = 0; kk < 8; kk++) {
            float a[8], b[8];
            *(float4*)(a)     = *(const float4*)(&As[kk][ty * 4]);
            *(float4*)(a + 4) = *(const float4*)(&As[kk][64 + ty * 4]);
            *(float4*)(b)     = *(const float4*)(&Bs[kk][tx * 4]);
            *(float4*)(b + 4) = *(const float4*)(&Bs[kk][64 + tx * 4]);
#pragma unroll
            for (int i = 0; i < 8; i++)
#pragma unroll
                for (int j = 0; j < 8; j++)
                    acc[i][j] = fmaf(a[i], b[j], acc[i][j]);
        }
    }

#pragma unroll
    for (int i = 0; i < 8; i++) {
        int r = row0 + ty * 4 + (i & 3) + ((i >> 2) << 6);
#pragma unroll
        for (int jg = 0; jg < 2; jg++) {
            int e0 = col0 + tx * 4 + jg * 64;
            float4 bb = *(const float4*)(Bv + e0);
            *(float4*)(out + (size_t)r * EDIM + e0) = make_float4(
                acc[i][jg * 4 + 0] + bb.x, acc[i][jg * 4 + 1] + bb.y,
                acc[i][jg * 4 + 2] + bb.z, acc[i][jg * 4 + 3] + bb.w);
        }
    }
}

// ============================================================================
extern "C" void kernel_launch(void* const* d_in, const int* in_sizes, int n_in,
                              void* d_out, int out_size)
{
    const float* query = (const float*)d_in[0];
    const float* key   = (const float*)d_in[1];
    const float* value = (const float*)d_in[2];
    const float* Wi    = (const float*)d_in[3];
    const float* Bi    = (const float*)d_in[4];
    const float* Wo    = (const float*)d_in[5];
    const float* Bo    = (const float*)d_in[6];
    const float* rq    = (const float*)d_in[7];
    const float* rk    = (const float*)d_in[8];
    const float* kmem  = (const float*)d_in[9];
    const float* vmem  = (const float*)d_in[10];
    const float* gate  = (const float*)d_in[11];
    const unsigned int* mmask_raw = (const unsigned int*)d_in[12];
    float* out = (float*)d_out;

    mask_decode_kernel<<<1, 256>>>(mmask_raw);
    qkv_kernel<<<dim3(4, 64, 3), 256>>>(query, key, value, Wi, Bi, rq, rk);
    scores_kernel<<<dim3(8, 8, 64), 256>>>();
    colsum_kernel<<<dim3(4, 64), 256>>>();
    attn_main_kernel<<<dim3(8, 64), 256>>>();
    attn_mem_kernel<<<dim3(16, 64), 256>>>(kmem, vmem, gate);
    outproj_kernel<<<dim3(4, 64), 256>>>(Wo, Bo, out);
}